// round 1
// baseline (speedup 1.0000x reference)
#include <cuda_runtime.h>
#include <cuda_bf16.h>
#include <math.h>

#define Bx 128
#define Lx 256
#define HIDx 768
#define HID2x 1536
#define CDIMx 192
#define SDIMx 128
#define NPROJx 128
#define FDIMx 321
#define BIGF 1000000000.0f

// ---------------- scratch (static device arrays; no allocation) ----------------
__device__ float g_rep[Bx * HID2x];                 // 786 KB
__device__ float g_Pt[(size_t)Bx * NPROJx * Lx];    // 16.8 MB, layout [b][p][l]
__device__ float g_feat[Bx * FDIMx];                // feat; col 320 = d_ot (atomicMax)
__device__ float g_partial[4 * Bx * 320];           // split-K partials for feature GEMM
__device__ int   g_mcnt[Bx];

// ================= K1: masks, counts, cls, mean0-mean1 -> rep =================
__global__ void k1_stats(const float* __restrict__ H,
                         const int* __restrict__ tt,
                         const int* __restrict__ m) {
    int b = blockIdx.x;
    int tid = threadIdx.x; // 256 threads
    __shared__ float sf0[Lx], sf1[Lx];
    __shared__ float sc0, sc1;

    int t = tt[b * Lx + tid];
    int mm = m[b * Lx + tid];
    sf0[tid] = (t == 0 && mm == 1) ? 1.f : 0.f;
    sf1[tid] = (t == 1 && mm == 1) ? 1.f : 0.f;
    __syncthreads();

    if (tid == 0) {
        int c0 = 0, c1 = 0;
        for (int l = 0; l < Lx; l++) { c0 += (sf0[l] > 0.5f); c1 += (sf1[l] > 0.5f); }
        g_mcnt[b] = min(c0, c1);
        sc0 = fmaxf((float)c0, 1.f);
        sc1 = fmaxf((float)c1, 1.f);
        g_feat[b * FDIMx + 320] = 0.f;   // init d_ot for atomicMax (values >= 0)
    }
    __syncthreads();

    const float* Hb = H + (size_t)b * Lx * HIDx;
    float s0[3] = {0.f, 0.f, 0.f}, s1[3] = {0.f, 0.f, 0.f};
    for (int l = 0; l < Lx; l++) {
        float f0 = sf0[l], f1 = sf1[l];
        const float* row = Hb + (size_t)l * HIDx;
#pragma unroll
        for (int q = 0; q < 3; q++) {
            float h = row[tid + q * 256];
            s0[q] += f0 * h;
            s1[q] += f1 * h;
        }
    }
    float inv0 = 1.f / sc0, inv1 = 1.f / sc1;
#pragma unroll
    for (int q = 0; q < 3; q++) {
        int h = tid + q * 256;
        g_rep[(size_t)b * HID2x + h]         = Hb[h];                       // cls = H[b,0,:]
        g_rep[(size_t)b * HID2x + HIDx + h]  = s0[q] * inv0 - s1[q] * inv1; // mean0-mean1
    }
}

// ================= K2: Pt[b][p][l] = sum_h H[b,l,h] * proj[p,h] =================
// Block: 256 threads, tile 64 l x 128 p, K-chunks of 16. fp32.
__global__ void __launch_bounds__(256) k2_gemm(const float* __restrict__ H,
                                               const float* __restrict__ proj) {
    __shared__ float Hs[16][64];
    __shared__ float Ps[16][128];

    int b = blockIdx.y;
    int l0 = blockIdx.x * 64;
    int tid = threadIdx.x;
    int tx = tid & 31;   // p-quad: p = tx*4 + j
    int ty = tid >> 5;   // l-octet: l = l0 + ty*8 + i

    float acc[8][4];
#pragma unroll
    for (int i = 0; i < 8; i++)
#pragma unroll
        for (int j = 0; j < 4; j++) acc[i][j] = 0.f;

    const float* Hbase = H + ((size_t)b * Lx + l0) * HIDx;

    for (int k0 = 0; k0 < HIDx; k0 += 16) {
        // load H tile (64 l x 16 k)
        {
            int l = tid >> 2;
            int kq = (tid & 3) * 4;
            float4 v = *reinterpret_cast<const float4*>(Hbase + (size_t)l * HIDx + k0 + kq);
            Hs[kq + 0][l] = v.x; Hs[kq + 1][l] = v.y;
            Hs[kq + 2][l] = v.z; Hs[kq + 3][l] = v.w;
        }
        // load proj tile (128 p x 16 k)
        {
            int p = tid >> 1;
            int kq = (tid & 1) * 8;
            const float* pb = proj + (size_t)p * HIDx + k0 + kq;
            float4 v0 = *reinterpret_cast<const float4*>(pb);
            float4 v1 = *reinterpret_cast<const float4*>(pb + 4);
            Ps[kq + 0][p] = v0.x; Ps[kq + 1][p] = v0.y;
            Ps[kq + 2][p] = v0.z; Ps[kq + 3][p] = v0.w;
            Ps[kq + 4][p] = v1.x; Ps[kq + 5][p] = v1.y;
            Ps[kq + 6][p] = v1.z; Ps[kq + 7][p] = v1.w;
        }
        __syncthreads();

#pragma unroll
        for (int k = 0; k < 16; k++) {
            float4 pv = *reinterpret_cast<const float4*>(&Ps[k][tx * 4]);
            float4 ha = *reinterpret_cast<const float4*>(&Hs[k][ty * 8]);
            float4 hb = *reinterpret_cast<const float4*>(&Hs[k][ty * 8 + 4]);
            float hv[8] = {ha.x, ha.y, ha.z, ha.w, hb.x, hb.y, hb.z, hb.w};
            float pj[4] = {pv.x, pv.y, pv.z, pv.w};
#pragma unroll
            for (int i = 0; i < 8; i++)
#pragma unroll
                for (int j = 0; j < 4; j++) acc[i][j] += hv[i] * pj[j];
        }
        __syncthreads();
    }

    size_t base = (size_t)b * NPROJx * Lx;
#pragma unroll
    for (int j = 0; j < 4; j++) {
        int p = tx * 4 + j;
        float* dst = g_Pt + base + (size_t)p * Lx + l0 + ty * 8;
        float4 o0 = make_float4(acc[0][j], acc[1][j], acc[2][j], acc[3][j]);
        float4 o1 = make_float4(acc[4][j], acc[5][j], acc[6][j], acc[7][j]);
        *reinterpret_cast<float4*>(dst) = o0;
        *reinterpret_cast<float4*>(dst + 4) = o1;
    }
}

// ================= K3: per-(b,p) bitonic sorts + matched-quantile mean |diff| =====
__device__ __forceinline__ void cex_asc(float& a, float& b) {
    float lo = fminf(a, b);
    float hi = fmaxf(a, b);
    a = lo; b = hi;
}

// Full ascending bitonic sort of 256 values: 8 registers per lane, idx = r*32 + lane.
__device__ __forceinline__ void sort256(float v[8], int lane) {
    const unsigned FULL = 0xffffffffu;
    for (int k = 2; k <= 256; k <<= 1) {
        for (int j = k >> 1; j > 0; j >>= 1) {
            if (j >= 32) {
                int jr = j >> 5;
                int kr = k >> 5;
#pragma unroll
                for (int r = 0; r < 8; r++) {
                    if ((r & jr) == 0) {
                        if ((r & kr) == 0) cex_asc(v[r], v[r | jr]);
                        else               cex_asc(v[r | jr], v[r]);
                    }
                }
            } else {
#pragma unroll
                for (int r = 0; r < 8; r++) {
                    int idx = r * 32 + lane;
                    float other = __shfl_xor_sync(FULL, v[r], j);
                    bool lower = (idx & j) == 0;
                    bool asc   = (idx & k) == 0;
                    bool takeMin = (lower == asc);
                    v[r] = takeMin ? fminf(v[r], other) : fmaxf(v[r], other);
                }
            }
        }
    }
}

__global__ void k3_sort(const int* __restrict__ tt, const int* __restrict__ m) {
    int b = blockIdx.y;
    int tid = threadIdx.x;          // 256 threads = 8 warps
    int warp = tid >> 5, lane = tid & 31;
    __shared__ int tag[Lx];

    int t = tt[b * Lx + tid];
    int mm = m[b * Lx + tid];
    tag[tid] = (mm == 1) ? t : 2;
    __syncthreads();

    int p = blockIdx.x * 8 + warp;
    const float* col = g_Pt + ((size_t)b * NPROJx + p) * Lx;

    float a[8], c[8];
#pragma unroll
    for (int r = 0; r < 8; r++) {
        int l = r * 32 + lane;
        float v = col[l];
        int tg = tag[l];
        a[r] = (tg == 0) ? v : BIGF;
        c[r] = (tg == 1) ? v : BIGF;
    }
    sort256(a, lane);
    sort256(c, lane);

    int mc = g_mcnt[b];
    float s = 0.f;
#pragma unroll
    for (int r = 0; r < 8; r++) {
        int idx = r * 32 + lane;
        if (idx < mc) s += fabsf(a[r] - c[r]);
    }
#pragma unroll
    for (int o = 16; o > 0; o >>= 1) s += __shfl_down_sync(0xffffffffu, s, o);

    if (lane == 0) {
        float mean = s / (float)max(mc, 1);
        atomicMax(reinterpret_cast<int*>(&g_feat[b * FDIMx + 320]), __float_as_int(mean));
    }
}

// ===== K4a: feature GEMM (split-K): partial[z][b][f] = sum_{k in chunk} rep*W =====
// Tile: 32 b x 64 f, K-chunk 384 per z. 256 threads, thread tile 2b x 4f.
__global__ void __launch_bounds__(256) k4a_featgemm(const float* __restrict__ Wc,
                                                    const float* __restrict__ Ws) {
    __shared__ float repS[16][32];
    __shared__ float wS[16][64];

    int ftile = blockIdx.x * 64;   // 0..4
    int btile = blockIdx.y * 32;   // 0..3
    int kc    = blockIdx.z * 384;  // 0..3
    int tid = threadIdx.x;
    int tx = tid & 15;   // f = ftile + tx*4 + j
    int ty = tid >> 4;   // b = btile + ty*2 + i

    float acc[2][4];
#pragma unroll
    for (int i = 0; i < 2; i++)
#pragma unroll
        for (int j = 0; j < 4; j++) acc[i][j] = 0.f;

    for (int k0 = 0; k0 < 384; k0 += 16) {
        // rep tile: 16 k x 32 b
#pragma unroll
        for (int q = 0; q < 2; q++) {
            int e = tid + q * 256;
            int kk = e & 15, bb = e >> 4;
            repS[kk][bb] = g_rep[(size_t)(btile + bb) * HID2x + kc + k0 + kk];
        }
        // W tile: 16 k x 64 f
#pragma unroll
        for (int q = 0; q < 4; q++) {
            int e = tid + q * 256;
            int kk = e & 15, ff = e >> 4;
            int f = ftile + ff;
            const float* Wr = (f < CDIMx) ? (Wc + (size_t)f * HID2x)
                                          : (Ws + (size_t)(f - CDIMx) * HID2x);
            wS[kk][ff] = Wr[kc + k0 + kk];
        }
        __syncthreads();

#pragma unroll
        for (int kk = 0; kk < 16; kk++) {
            float4 wv = *reinterpret_cast<const float4*>(&wS[kk][tx * 4]);
            float r0 = repS[kk][ty * 2];
            float r1 = repS[kk][ty * 2 + 1];
            acc[0][0] += r0 * wv.x; acc[0][1] += r0 * wv.y;
            acc[0][2] += r0 * wv.z; acc[0][3] += r0 * wv.w;
            acc[1][0] += r1 * wv.x; acc[1][1] += r1 * wv.y;
            acc[1][2] += r1 * wv.z; acc[1][3] += r1 * wv.w;
        }
        __syncthreads();
    }

#pragma unroll
    for (int i = 0; i < 2; i++) {
        int bb = btile + ty * 2 + i;
        float4 o = make_float4(acc[i][0], acc[i][1], acc[i][2], acc[i][3]);
        *reinterpret_cast<float4*>(&g_partial[((size_t)blockIdx.z * Bx + bb) * 320 + ftile + tx * 4]) = o;
    }
}

// ===== K4b: combine split-K partials, add bias, apply sigmoid gate -> feat =======
__global__ void k4b_combine(const float* __restrict__ bc,
                            const float* __restrict__ bs,
                            const float* __restrict__ gate) {
    int b = blockIdx.x;
    int f = threadIdx.x; // 320 threads
    float s = 0.f;
#pragma unroll
    for (int z = 0; z < 4; z++) s += g_partial[((size_t)z * Bx + b) * 320 + f];
    float g = 1.f / (1.f + expf(-gate[0]));
    float v;
    if (f < CDIMx) v = (s + bc[f]) * (1.f - g);
    else           v = (s + bs[f - CDIMx]) * g;
    g_feat[b * FDIMx + f] = v;
}

// ================= K5: LayerNorm(321) + classifier (2 outputs) ===================
__device__ __forceinline__ float blockReduceSum(float val, float* sbuf) {
    int tid = threadIdx.x;
#pragma unroll
    for (int o = 16; o > 0; o >>= 1) val += __shfl_down_sync(0xffffffffu, val, o);
    if ((tid & 31) == 0) sbuf[tid >> 5] = val;
    __syncthreads();
    if (tid < 32) {
        int nw = (blockDim.x + 31) >> 5;
        float r = (tid < nw) ? sbuf[tid] : 0.f;
#pragma unroll
        for (int o = 16; o > 0; o >>= 1) r += __shfl_down_sync(0xffffffffu, r, o);
        if (tid == 0) sbuf[32] = r;
    }
    __syncthreads();
    float out = sbuf[32];
    __syncthreads();
    return out;
}

__global__ void k5_ln_cls(const float* __restrict__ ln_g,
                          const float* __restrict__ ln_b,
                          const float* __restrict__ Wcls,
                          const float* __restrict__ bcls,
                          float* __restrict__ out) {
    __shared__ float sbuf[33];
    int b = blockIdx.x;
    int f = threadIdx.x; // 384 threads
    bool act = (f < FDIMx);
    float x = act ? g_feat[b * FDIMx + f] : 0.f;

    float S  = blockReduceSum(x, sbuf);
    float SS = blockReduceSum(x * x, sbuf);
    float mean = S / (float)FDIMx;
    float var  = SS / (float)FDIMx - mean * mean;
    float inv  = rsqrtf(var + 1e-5f);

    float nrm = act ? ((x - mean) * inv * ln_g[f] + ln_b[f]) : 0.f;
    float w0 = act ? Wcls[f] : 0.f;
    float w1 = act ? Wcls[FDIMx + f] : 0.f;

    float s0 = blockReduceSum(nrm * w0, sbuf);
    float s1 = blockReduceSum(nrm * w1, sbuf);
    if (f == 0) {
        out[b * 2 + 0] = s0 + bcls[0];
        out[b * 2 + 1] = s1 + bcls[1];
    }
}

// =================================== launch ======================================
extern "C" void kernel_launch(void* const* d_in, const int* in_sizes, int n_in,
                              void* d_out, int out_size) {
    const float* H    = (const float*)d_in[0];
    const int*   tt   = (const int*)d_in[1];
    const int*   m    = (const int*)d_in[2];
    const float* Wc   = (const float*)d_in[3];
    const float* bc   = (const float*)d_in[4];
    const float* Ws   = (const float*)d_in[5];
    const float* bs   = (const float*)d_in[6];
    const float* gate = (const float*)d_in[7];
    const float* ln_g = (const float*)d_in[8];
    const float* ln_b = (const float*)d_in[9];
    const float* Wcls = (const float*)d_in[10];
    const float* bcls = (const float*)d_in[11];
    const float* proj = (const float*)d_in[12];
    float* out = (float*)d_out;

    k1_stats<<<Bx, 256>>>(H, tt, m);
    k2_gemm<<<dim3(4, Bx), 256>>>(H, proj);
    k3_sort<<<dim3(16, Bx), 256>>>(tt, m);
    k4a_featgemm<<<dim3(5, 4, 4), 256>>>(Wc, Ws);
    k4b_combine<<<Bx, 320>>>(bc, bs, gate);
    k5_ln_cls<<<Bx, 384>>>(ln_g, ln_b, Wcls, bcls, out);
}

// round 2
// speedup vs baseline: 1.1363x; 1.1363x over previous
#include <cuda_runtime.h>
#include <cuda_bf16.h>
#include <math.h>

#define Bx 128
#define Lx 256
#define HIDx 768
#define HID2x 1536
#define CDIMx 192
#define SDIMx 128
#define NPROJx 128
#define FDIMx 321
#define BIGF 1000000000.0f

// ---------------- scratch (static device arrays; no allocation) ----------------
__device__ float g_rep[Bx * HID2x];
__device__ float g_Pt[(size_t)Bx * NPROJx * Lx];    // [b][p][l]
__device__ float g_feat[Bx * FDIMx];                // only col 320 (d_ot) used
__device__ float g_partial[8 * Bx * 320];           // split-K partials (z=8)
__device__ int   g_mcnt[Bx];

// ---------------- packed f32x2 helpers ----------------
typedef unsigned long long u64;

#define FMA2(d, a, b) \
    asm("fma.rn.f32x2 %0, %1, %2, %0;" : "+l"(d) : "l"(a), "l"(b))

__device__ __forceinline__ void dup2(u64 v, u64& a, u64& b) {
    unsigned lo, hi;
    asm("mov.b64 {%0,%1}, %2;" : "=r"(lo), "=r"(hi) : "l"(v));
    asm("mov.b64 %0, {%1,%1};" : "=l"(a) : "r"(lo));
    asm("mov.b64 %0, {%1,%1};" : "=l"(b) : "r"(hi));
}

// ================= K1: masks, counts, cls, mean0-mean1 -> rep =================
// grid (B, 3): block handles 256-wide h-chunk c for batch b.
__global__ void k1_stats(const float* __restrict__ H,
                         const int* __restrict__ tt,
                         const int* __restrict__ m) {
    int b = blockIdx.x;
    int c = blockIdx.y;
    int tid = threadIdx.x; // 256
    __shared__ float sf0[Lx], sf1[Lx];
    __shared__ float sc0, sc1;

    int t = tt[b * Lx + tid];
    int mm = m[b * Lx + tid];
    sf0[tid] = (t == 0 && mm == 1) ? 1.f : 0.f;
    sf1[tid] = (t == 1 && mm == 1) ? 1.f : 0.f;
    __syncthreads();

    if (tid == 0) {
        int c0 = 0, c1 = 0;
        for (int l = 0; l < Lx; l++) { c0 += (sf0[l] > 0.5f); c1 += (sf1[l] > 0.5f); }
        if (c == 0) {
            g_mcnt[b] = min(c0, c1);
            g_feat[b * FDIMx + 320] = 0.f;   // init d_ot for atomicMax (vals >= 0)
        }
        sc0 = fmaxf((float)c0, 1.f);
        sc1 = fmaxf((float)c1, 1.f);
    }
    __syncthreads();

    int h = c * 256 + tid;
    const float* Hb = H + (size_t)b * Lx * HIDx;
    float s0 = 0.f, s1 = 0.f;
#pragma unroll 4
    for (int l = 0; l < Lx; l++) {
        float v = Hb[(size_t)l * HIDx + h];
        s0 += sf0[l] * v;
        s1 += sf1[l] * v;
    }
    g_rep[(size_t)b * HID2x + h]        = Hb[h];                  // cls
    g_rep[(size_t)b * HID2x + HIDx + h] = s0 / sc0 - s1 / sc1;    // mean0-mean1
}

// ================= K2: Pt[b][p][l] = sum_h H[b,l,h] * proj[p,h] =================
// Block: 256 threads, tile 128 l x 128 p, K-chunks of 16, packed f32x2 FMA.
// Thread tile 8l x 8p, acc packed along l (4 x 8 f32x2).
__global__ void __launch_bounds__(256, 2) k2_gemm(const float* __restrict__ H,
                                                  const float* __restrict__ proj) {
    __shared__ float Hs[16][128];
    __shared__ float Ps[16][128];

    int b = blockIdx.y;
    int l0 = blockIdx.x * 128;
    int tid = threadIdx.x;
    int tx = tid & 15;   // p group: p = tx*8 + j
    int ty = tid >> 4;   // l group: l = l0 + ty*8 + i

    const float* Hbase = H + ((size_t)b * Lx + l0) * HIDx;

    // loader: each thread loads 8 consecutive floats of one row
    int lrow = tid >> 1;
    int lcol = (tid & 1) * 8;

    u64 acc[4][8];
#pragma unroll
    for (int i = 0; i < 4; i++)
#pragma unroll
        for (int j = 0; j < 8; j++) acc[i][j] = 0ull;

    float4 hb0, hb1, pb0, pb1;
    {
        const float* hp = Hbase + (size_t)lrow * HIDx + lcol;
        hb0 = *reinterpret_cast<const float4*>(hp);
        hb1 = *reinterpret_cast<const float4*>(hp + 4);
        const float* pp = proj + (size_t)lrow * HIDx + lcol;
        pb0 = *reinterpret_cast<const float4*>(pp);
        pb1 = *reinterpret_cast<const float4*>(pp + 4);
    }

    for (int cidx = 0; cidx < 48; cidx++) {
        // store prefetched regs to smem (transposed)
        Hs[lcol + 0][lrow] = hb0.x; Hs[lcol + 1][lrow] = hb0.y;
        Hs[lcol + 2][lrow] = hb0.z; Hs[lcol + 3][lrow] = hb0.w;
        Hs[lcol + 4][lrow] = hb1.x; Hs[lcol + 5][lrow] = hb1.y;
        Hs[lcol + 6][lrow] = hb1.z; Hs[lcol + 7][lrow] = hb1.w;
        Ps[lcol + 0][lrow] = pb0.x; Ps[lcol + 1][lrow] = pb0.y;
        Ps[lcol + 2][lrow] = pb0.z; Ps[lcol + 3][lrow] = pb0.w;
        Ps[lcol + 4][lrow] = pb1.x; Ps[lcol + 5][lrow] = pb1.y;
        Ps[lcol + 6][lrow] = pb1.z; Ps[lcol + 7][lrow] = pb1.w;
        __syncthreads();

        if (cidx + 1 < 48) {
            int k0 = (cidx + 1) * 16;
            const float* hp = Hbase + (size_t)lrow * HIDx + k0 + lcol;
            hb0 = *reinterpret_cast<const float4*>(hp);
            hb1 = *reinterpret_cast<const float4*>(hp + 4);
            const float* pp = proj + (size_t)lrow * HIDx + k0 + lcol;
            pb0 = *reinterpret_cast<const float4*>(pp);
            pb1 = *reinterpret_cast<const float4*>(pp + 4);
        }

#pragma unroll
        for (int k = 0; k < 16; k++) {
            const u64* hp2 = reinterpret_cast<const u64*>(&Hs[k][ty * 8]);
            u64 h0 = hp2[0], h1 = hp2[1], h2 = hp2[2], h3 = hp2[3];
            const u64* pp2 = reinterpret_cast<const u64*>(&Ps[k][tx * 8]);
#pragma unroll
            for (int jq = 0; jq < 4; jq++) {
                u64 q = pp2[jq];
                u64 pa, pb;
                dup2(q, pa, pb);
                FMA2(acc[0][jq * 2],     h0, pa);
                FMA2(acc[1][jq * 2],     h1, pa);
                FMA2(acc[2][jq * 2],     h2, pa);
                FMA2(acc[3][jq * 2],     h3, pa);
                FMA2(acc[0][jq * 2 + 1], h0, pb);
                FMA2(acc[1][jq * 2 + 1], h1, pb);
                FMA2(acc[2][jq * 2 + 1], h2, pb);
                FMA2(acc[3][jq * 2 + 1], h3, pb);
            }
        }
        __syncthreads();
    }

    size_t base = (size_t)b * NPROJx * Lx;
#pragma unroll
    for (int j = 0; j < 8; j++) {
        int p = tx * 8 + j;
        u64* dst = reinterpret_cast<u64*>(g_Pt + base + (size_t)p * Lx + l0 + ty * 8);
        dst[0] = acc[0][j];
        dst[1] = acc[1][j];
        dst[2] = acc[2][j];
        dst[3] = acc[3][j];
    }
}

// ================= K3: per-(b,p) bitonic sorts + matched-quantile mean |diff| =====
__device__ __forceinline__ void cex_asc(float& a, float& b) {
    float lo = fminf(a, b);
    float hi = fmaxf(a, b);
    a = lo; b = hi;
}

__device__ __forceinline__ void sort256(float v[8], int lane) {
    const unsigned FULL = 0xffffffffu;
    for (int k = 2; k <= 256; k <<= 1) {
        for (int j = k >> 1; j > 0; j >>= 1) {
            if (j >= 32) {
                int jr = j >> 5;
                int kr = k >> 5;
#pragma unroll
                for (int r = 0; r < 8; r++) {
                    if ((r & jr) == 0) {
                        if ((r & kr) == 0) cex_asc(v[r], v[r | jr]);
                        else               cex_asc(v[r | jr], v[r]);
                    }
                }
            } else {
#pragma unroll
                for (int r = 0; r < 8; r++) {
                    int idx = r * 32 + lane;
                    float other = __shfl_xor_sync(FULL, v[r], j);
                    bool lower = (idx & j) == 0;
                    bool asc   = (idx & k) == 0;
                    bool takeMin = (lower == asc);
                    v[r] = takeMin ? fminf(v[r], other) : fmaxf(v[r], other);
                }
            }
        }
    }
}

__global__ void k3_sort(const int* __restrict__ tt, const int* __restrict__ m) {
    int b = blockIdx.y;
    int tid = threadIdx.x;          // 256 threads = 8 warps
    int warp = tid >> 5, lane = tid & 31;
    __shared__ int tag[Lx];

    int t = tt[b * Lx + tid];
    int mm = m[b * Lx + tid];
    tag[tid] = (mm == 1) ? t : 2;
    __syncthreads();

    int p = blockIdx.x * 8 + warp;
    const float* col = g_Pt + ((size_t)b * NPROJx + p) * Lx;

    float a[8], c[8];
#pragma unroll
    for (int r = 0; r < 8; r++) {
        int l = r * 32 + lane;
        float v = col[l];
        int tg = tag[l];
        a[r] = (tg == 0) ? v : BIGF;
        c[r] = (tg == 1) ? v : BIGF;
    }
    sort256(a, lane);
    sort256(c, lane);

    int mc = g_mcnt[b];
    float s = 0.f;
#pragma unroll
    for (int r = 0; r < 8; r++) {
        int idx = r * 32 + lane;
        if (idx < mc) s += fabsf(a[r] - c[r]);
    }
#pragma unroll
    for (int o = 16; o > 0; o >>= 1) s += __shfl_down_sync(0xffffffffu, s, o);

    if (lane == 0) {
        float mean = s / (float)max(mc, 1);
        atomicMax(reinterpret_cast<int*>(&g_feat[b * FDIMx + 320]), __float_as_int(mean));
    }
}

// ===== K4a: feature GEMM (split-K z=8): partial[z][b][f] = sum_k rep*W =====
__global__ void __launch_bounds__(256) k4a_featgemm(const float* __restrict__ Wc,
                                                    const float* __restrict__ Ws) {
    __shared__ float repS[16][32];
    __shared__ float wS[16][64];

    int ftile = blockIdx.x * 64;   // 0..4
    int btile = blockIdx.y * 32;   // 0..3
    int kc    = blockIdx.z * 192;  // 0..7
    int tid = threadIdx.x;
    int tx = tid & 15;   // f = ftile + tx*4 + j
    int ty = tid >> 4;   // b = btile + ty*2 + i

    float acc[2][4];
#pragma unroll
    for (int i = 0; i < 2; i++)
#pragma unroll
        for (int j = 0; j < 4; j++) acc[i][j] = 0.f;

    for (int k0 = 0; k0 < 192; k0 += 16) {
#pragma unroll
        for (int q = 0; q < 2; q++) {
            int e = tid + q * 256;
            int kk = e & 15, bb = e >> 4;
            repS[kk][bb] = g_rep[(size_t)(btile + bb) * HID2x + kc + k0 + kk];
        }
#pragma unroll
        for (int q = 0; q < 4; q++) {
            int e = tid + q * 256;
            int kk = e & 15, ff = e >> 4;
            int f = ftile + ff;
            const float* Wr = (f < CDIMx) ? (Wc + (size_t)f * HID2x)
                                          : (Ws + (size_t)(f - CDIMx) * HID2x);
            wS[kk][ff] = Wr[kc + k0 + kk];
        }
        __syncthreads();

#pragma unroll
        for (int kk = 0; kk < 16; kk++) {
            float4 wv = *reinterpret_cast<const float4*>(&wS[kk][tx * 4]);
            float r0 = repS[kk][ty * 2];
            float r1 = repS[kk][ty * 2 + 1];
            acc[0][0] += r0 * wv.x; acc[0][1] += r0 * wv.y;
            acc[0][2] += r0 * wv.z; acc[0][3] += r0 * wv.w;
            acc[1][0] += r1 * wv.x; acc[1][1] += r1 * wv.y;
            acc[1][2] += r1 * wv.z; acc[1][3] += r1 * wv.w;
        }
        __syncthreads();
    }

#pragma unroll
    for (int i = 0; i < 2; i++) {
        int bb = btile + ty * 2 + i;
        float4 o = make_float4(acc[i][0], acc[i][1], acc[i][2], acc[i][3]);
        *reinterpret_cast<float4*>(&g_partial[((size_t)blockIdx.z * Bx + bb) * 320 + ftile + tx * 4]) = o;
    }
}

// ===== K5: combine split-K + gate, LayerNorm(321), classifier (fused) =========
__device__ __forceinline__ float blockReduceSum(float val, float* sbuf) {
    int tid = threadIdx.x;
#pragma unroll
    for (int o = 16; o > 0; o >>= 1) val += __shfl_down_sync(0xffffffffu, val, o);
    if ((tid & 31) == 0) sbuf[tid >> 5] = val;
    __syncthreads();
    if (tid < 32) {
        int nw = (blockDim.x + 31) >> 5;
        float r = (tid < nw) ? sbuf[tid] : 0.f;
#pragma unroll
        for (int o = 16; o > 0; o >>= 1) r += __shfl_down_sync(0xffffffffu, r, o);
        if (tid == 0) sbuf[32] = r;
    }
    __syncthreads();
    float out = sbuf[32];
    __syncthreads();
    return out;
}

__global__ void k5_ln_cls(const float* __restrict__ bc,
                          const float* __restrict__ bs,
                          const float* __restrict__ gate,
                          const float* __restrict__ ln_g,
                          const float* __restrict__ ln_b,
                          const float* __restrict__ Wcls,
                          const float* __restrict__ bcls,
                          float* __restrict__ out) {
    __shared__ float sbuf[33];
    int b = blockIdx.x;
    int f = threadIdx.x; // 384 threads
    bool act = (f < FDIMx);

    float x = 0.f;
    if (f < 320) {
        float s = 0.f;
#pragma unroll
        for (int z = 0; z < 8; z++) s += g_partial[((size_t)z * Bx + b) * 320 + f];
        float g = 1.f / (1.f + expf(-gate[0]));
        if (f < CDIMx) x = (s + bc[f]) * (1.f - g);
        else           x = (s + bs[f - CDIMx]) * g;
    } else if (f == 320) {
        x = g_feat[b * FDIMx + 320];
    }

    float S  = blockReduceSum(x, sbuf);
    float SS = blockReduceSum(x * x, sbuf);
    float mean = S / (float)FDIMx;
    float var  = SS / (float)FDIMx - mean * mean;
    float inv  = rsqrtf(var + 1e-5f);

    float nrm = act ? ((x - mean) * inv * ln_g[f] + ln_b[f]) : 0.f;
    float w0 = act ? Wcls[f] : 0.f;
    float w1 = act ? Wcls[FDIMx + f] : 0.f;

    float s0 = blockReduceSum(nrm * w0, sbuf);
    float s1 = blockReduceSum(nrm * w1, sbuf);
    if (f == 0) {
        out[b * 2 + 0] = s0 + bcls[0];
        out[b * 2 + 1] = s1 + bcls[1];
    }
}

// =================================== launch ======================================
extern "C" void kernel_launch(void* const* d_in, const int* in_sizes, int n_in,
                              void* d_out, int out_size) {
    const float* H    = (const float*)d_in[0];
    const int*   tt   = (const int*)d_in[1];
    const int*   m    = (const int*)d_in[2];
    const float* Wc   = (const float*)d_in[3];
    const float* bc   = (const float*)d_in[4];
    const float* Ws   = (const float*)d_in[5];
    const float* bs   = (const float*)d_in[6];
    const float* gate = (const float*)d_in[7];
    const float* ln_g = (const float*)d_in[8];
    const float* ln_b = (const float*)d_in[9];
    const float* Wcls = (const float*)d_in[10];
    const float* bcls = (const float*)d_in[11];
    const float* proj = (const float*)d_in[12];
    float* out = (float*)d_out;

    k1_stats<<<dim3(Bx, 3), 256>>>(H, tt, m);
    k2_gemm<<<dim3(2, Bx), 256>>>(H, proj);
    k3_sort<<<dim3(16, Bx), 256>>>(tt, m);
    k4a_featgemm<<<dim3(5, 4, 8), 256>>>(Wc, Ws);
    k5_ln_cls<<<Bx, 384>>>(bc, bs, gate, ln_g, ln_b, Wcls, bcls, out);
}

// round 4
// speedup vs baseline: 1.2767x; 1.1235x over previous
#include <cuda_runtime.h>
#include <cuda_bf16.h>
#include <math.h>
#include <stdint.h>

#define Bx 128
#define Lx 256
#define HIDx 768
#define HID2x 1536
#define CDIMx 192
#define SDIMx 128
#define NPROJx 128
#define FDIMx 321
#define BIGF 1000000000.0f

// ---------------- scratch ----------------
__device__ float g_rep[Bx * HID2x];
__device__ float g_Pt[(size_t)Bx * NPROJx * Lx];    // [b][p][l]
__device__ float g_feat[Bx * FDIMx];                // only col 320 (d_ot) used
__device__ float g_partial[16 * Bx * 320];          // split-K partials (z=16)
__device__ int   g_mcnt[Bx];

// ================= K1: masks, counts, cls, mean0-mean1 -> rep =================
__global__ void k1_stats(const float* __restrict__ H,
                         const int* __restrict__ tt,
                         const int* __restrict__ m) {
    int b = blockIdx.x;
    int c = blockIdx.y;
    int tid = threadIdx.x; // 256
    __shared__ float sf0[Lx], sf1[Lx];
    __shared__ float sc0, sc1;

    int t = tt[b * Lx + tid];
    int mm = m[b * Lx + tid];
    sf0[tid] = (t == 0 && mm == 1) ? 1.f : 0.f;
    sf1[tid] = (t == 1 && mm == 1) ? 1.f : 0.f;
    __syncthreads();

    if (tid == 0) {
        int c0 = 0, c1 = 0;
        for (int l = 0; l < Lx; l++) { c0 += (sf0[l] > 0.5f); c1 += (sf1[l] > 0.5f); }
        if (c == 0) {
            g_mcnt[b] = min(c0, c1);
            g_feat[b * FDIMx + 320] = 0.f;
        }
        sc0 = fmaxf((float)c0, 1.f);
        sc1 = fmaxf((float)c1, 1.f);
    }
    __syncthreads();

    int h = c * 256 + tid;
    const float* Hb = H + (size_t)b * Lx * HIDx;
    float s0 = 0.f, s1 = 0.f;
#pragma unroll 4
    for (int l = 0; l < Lx; l++) {
        float v = Hb[(size_t)l * HIDx + h];
        s0 += sf0[l] * v;
        s1 += sf1[l] * v;
    }
    g_rep[(size_t)b * HID2x + h]        = Hb[h];
    g_rep[(size_t)b * HID2x + HIDx + h] = s0 / sc0 - s1 / sc1;
}

// ============ K2 (mma.sync tf32): Pt[b][p][l] = sum_h proj[p,h]*H[b,l,h] ============
// CTA = (b, l-half). D[M=128 l][N=128 p], K=768 in 24 chunks of 32. Double-buffered.
#define K2_PAD 136
#define K2_BUF (32 * K2_PAD)          // u32 elems per tile buffer
#define K2_SMEM (4 * K2_BUF * 4)      // bytes: As0,Bs0,As1,Bs1

__device__ __forceinline__ uint32_t cvt_tf32(float f) {
    uint32_t r;
    asm("cvt.rna.tf32.f32 %0, %1;" : "=r"(r) : "f"(f));
    return r;
}

__device__ __forceinline__ void mma8(float* d, const uint32_t* a, const uint32_t* b) {
    asm volatile(
        "mma.sync.aligned.m16n8k8.row.col.f32.tf32.tf32.f32 "
        "{%0,%1,%2,%3}, {%4,%5,%6,%7}, {%8,%9}, {%0,%1,%2,%3};"
        : "+f"(d[0]), "+f"(d[1]), "+f"(d[2]), "+f"(d[3])
        : "r"(a[0]), "r"(a[1]), "r"(a[2]), "r"(a[3]), "r"(b[0]), "r"(b[1]));
}

__device__ __forceinline__ void k2_load(const float* __restrict__ Hb,
                                        const float* __restrict__ proj,
                                        int kbase, int ll, int s0,
                                        float4 rA[2][2], float4 rB[2][2]) {
#pragma unroll
    for (int it = 0; it < 2; it++) {
        int sg = s0 + it * 2;
        const float* pa = Hb + (size_t)ll * HIDx + kbase + sg * 8;
        rA[it][0] = *reinterpret_cast<const float4*>(pa);
        rA[it][1] = *reinterpret_cast<const float4*>(pa + 4);
        const float* pb = proj + (size_t)ll * HIDx + kbase + sg * 8;
        rB[it][0] = *reinterpret_cast<const float4*>(pb);
        rB[it][1] = *reinterpret_cast<const float4*>(pb + 4);
    }
}

__device__ __forceinline__ void k2_store(uint32_t* __restrict__ A,
                                         uint32_t* __restrict__ B,
                                         int ll, int s0,
                                         float4 rA[2][2], float4 rB[2][2]) {
#pragma unroll
    for (int it = 0; it < 2; it++) {
        int kb = (s0 + it * 2) * 8;
        float fa[8] = {rA[it][0].x, rA[it][0].y, rA[it][0].z, rA[it][0].w,
                       rA[it][1].x, rA[it][1].y, rA[it][1].z, rA[it][1].w};
        float fb[8] = {rB[it][0].x, rB[it][0].y, rB[it][0].z, rB[it][0].w,
                       rB[it][1].x, rB[it][1].y, rB[it][1].z, rB[it][1].w};
#pragma unroll
        for (int j = 0; j < 8; j++) {
            A[(kb + j) * K2_PAD + ll] = cvt_tf32(fa[j]);
            B[(kb + j) * K2_PAD + ll] = cvt_tf32(fb[j]);
        }
    }
}

__global__ void __launch_bounds__(256, 1) k2_mma(const float* __restrict__ H,
                                                 const float* __restrict__ proj) {
    extern __shared__ uint32_t sm[];
    uint32_t* Abuf[2] = {sm,              sm + 2 * K2_BUF};
    uint32_t* Bbuf[2] = {sm + K2_BUF,     sm + 3 * K2_BUF};

    int b = blockIdx.x;
    int l0 = blockIdx.y * 128;
    int tid = threadIdx.x;
    int wid = tid >> 5, lane = tid & 31;
    int gid = lane >> 2, tig = lane & 3;
    int warp_l = (wid >> 2) * 64;   // 0 or 64
    int warp_p = (wid & 3) * 32;    // 0,32,64,96

    const float* Hb = H + ((size_t)b * Lx + l0) * HIDx;
    int ll = tid & 127;
    int s0 = tid >> 7;

    float acc[4][4][4];
#pragma unroll
    for (int i = 0; i < 4; i++)
#pragma unroll
        for (int j = 0; j < 4; j++)
#pragma unroll
            for (int r = 0; r < 4; r++) acc[i][j][r] = 0.f;

    float4 rA[2][2], rB[2][2];
    k2_load(Hb, proj, 0, ll, s0, rA, rB);
    k2_store(Abuf[0], Bbuf[0], ll, s0, rA, rB);
    __syncthreads();

    for (int c = 0; c < 24; c++) {
        int buf = c & 1;
        if (c < 23) k2_load(Hb, proj, (c + 1) * 32, ll, s0, rA, rB);

        const uint32_t* Ab = Abuf[buf];
        const uint32_t* Bb = Bbuf[buf];
#pragma unroll
        for (int ks = 0; ks < 4; ks++) {
            int kk = ks * 8;
            uint32_t af[4][4];
            uint32_t bf[4][2];
            const uint32_t* Ak  = Ab + (kk + tig) * K2_PAD;
            const uint32_t* Ak4 = Ab + (kk + tig + 4) * K2_PAD;
#pragma unroll
            for (int i = 0; i < 4; i++) {
                int row = warp_l + i * 16 + gid;
                af[i][0] = Ak[row];
                af[i][1] = Ak[row + 8];
                af[i][2] = Ak4[row];
                af[i][3] = Ak4[row + 8];
            }
            const uint32_t* Bk  = Bb + (kk + tig) * K2_PAD;
            const uint32_t* Bk4 = Bb + (kk + tig + 4) * K2_PAD;
#pragma unroll
            for (int j = 0; j < 4; j++) {
                int col = warp_p + j * 8 + gid;
                bf[j][0] = Bk[col];
                bf[j][1] = Bk4[col];
            }
#pragma unroll
            for (int i = 0; i < 4; i++)
#pragma unroll
                for (int j = 0; j < 4; j++) mma8(acc[i][j], af[i], bf[j]);
        }

        if (c < 23) {
            k2_store(Abuf[1 - buf], Bbuf[1 - buf], ll, s0, rA, rB);
            __syncthreads();
        }
    }

    // epilogue: D[l][p] -> g_Pt[b][p][l]
    size_t base = (size_t)b * NPROJx * Lx;
#pragma unroll
    for (int i = 0; i < 4; i++) {
        int lg = l0 + warp_l + i * 16 + gid;
#pragma unroll
        for (int j = 0; j < 4; j++) {
            int p0 = warp_p + j * 8 + tig * 2;
            g_Pt[base + (size_t)p0 * Lx + lg]           = acc[i][j][0];
            g_Pt[base + (size_t)(p0 + 1) * Lx + lg]     = acc[i][j][1];
            g_Pt[base + (size_t)p0 * Lx + lg + 8]       = acc[i][j][2];
            g_Pt[base + (size_t)(p0 + 1) * Lx + lg + 8] = acc[i][j][3];
        }
    }
}

// ================= K3: per-(b,p) bitonic sorts + mean |diff| =====
__device__ __forceinline__ void cex_asc(float& a, float& b) {
    float lo = fminf(a, b);
    float hi = fmaxf(a, b);
    a = lo; b = hi;
}

__device__ __forceinline__ void sort256(float v[8], int lane) {
    const unsigned FULL = 0xffffffffu;
    for (int k = 2; k <= 256; k <<= 1) {
        for (int j = k >> 1; j > 0; j >>= 1) {
            if (j >= 32) {
                int jr = j >> 5;
                int kr = k >> 5;
#pragma unroll
                for (int r = 0; r < 8; r++) {
                    if ((r & jr) == 0) {
                        if ((r & kr) == 0) cex_asc(v[r], v[r | jr]);
                        else               cex_asc(v[r | jr], v[r]);
                    }
                }
            } else {
#pragma unroll
                for (int r = 0; r < 8; r++) {
                    int idx = r * 32 + lane;
                    float other = __shfl_xor_sync(FULL, v[r], j);
                    bool lower = (idx & j) == 0;
                    bool asc   = (idx & k) == 0;
                    bool takeMin = (lower == asc);
                    v[r] = takeMin ? fminf(v[r], other) : fmaxf(v[r], other);
                }
            }
        }
    }
}

__global__ void k3_sort(const int* __restrict__ tt, const int* __restrict__ m) {
    int b = blockIdx.y;
    int tid = threadIdx.x;          // 256 threads = 8 warps
    int warp = tid >> 5, lane = tid & 31;
    __shared__ int tag[Lx];

    int t = tt[b * Lx + tid];
    int mm = m[b * Lx + tid];
    tag[tid] = (mm == 1) ? t : 2;
    __syncthreads();

    int p = blockIdx.x * 8 + warp;
    const float* col = g_Pt + ((size_t)b * NPROJx + p) * Lx;

    float a[8], c[8];
#pragma unroll
    for (int r = 0; r < 8; r++) {
        int l = r * 32 + lane;
        float v = col[l];
        int tg = tag[l];
        a[r] = (tg == 0) ? v : BIGF;
        c[r] = (tg == 1) ? v : BIGF;
    }
    sort256(a, lane);
    sort256(c, lane);

    int mc = g_mcnt[b];
    float s = 0.f;
#pragma unroll
    for (int r = 0; r < 8; r++) {
        int idx = r * 32 + lane;
        if (idx < mc) s += fabsf(a[r] - c[r]);
    }
#pragma unroll
    for (int o = 16; o > 0; o >>= 1) s += __shfl_down_sync(0xffffffffu, s, o);

    if (lane == 0) {
        float mean = s / (float)max(mc, 1);
        atomicMax(reinterpret_cast<int*>(&g_feat[b * FDIMx + 320]), __float_as_int(mean));
    }
}

// ===== K4a: feature GEMM (split-K z=16): partial[z][b][f] = sum_k rep*W =====
__global__ void __launch_bounds__(256) k4a_featgemm(const float* __restrict__ Wc,
                                                    const float* __restrict__ Ws) {
    __shared__ float repS[16][32];
    __shared__ float wS[16][64];

    int ftile = blockIdx.x * 64;   // 0..4
    int btile = blockIdx.y * 32;   // 0..3
    int kc    = blockIdx.z * 96;   // 0..15
    int tid = threadIdx.x;
    int tx = tid & 15;
    int ty = tid >> 4;

    float acc[2][4];
#pragma unroll
    for (int i = 0; i < 2; i++)
#pragma unroll
        for (int j = 0; j < 4; j++) acc[i][j] = 0.f;

    for (int k0 = 0; k0 < 96; k0 += 16) {
#pragma unroll
        for (int q = 0; q < 2; q++) {
            int e = tid + q * 256;
            int kk = e & 15, bb = e >> 4;
            repS[kk][bb] = g_rep[(size_t)(btile + bb) * HID2x + kc + k0 + kk];
        }
#pragma unroll
        for (int q = 0; q < 4; q++) {
            int e = tid + q * 256;
            int kk = e & 15, ff = e >> 4;
            int f = ftile + ff;
            const float* Wr = (f < CDIMx) ? (Wc + (size_t)f * HID2x)
                                          : (Ws + (size_t)(f - CDIMx) * HID2x);
            wS[kk][ff] = Wr[kc + k0 + kk];
        }
        __syncthreads();

#pragma unroll
        for (int kk = 0; kk < 16; kk++) {
            float4 wv = *reinterpret_cast<const float4*>(&wS[kk][tx * 4]);
            float r0 = repS[kk][ty * 2];
            float r1 = repS[kk][ty * 2 + 1];
            acc[0][0] += r0 * wv.x; acc[0][1] += r0 * wv.y;
            acc[0][2] += r0 * wv.z; acc[0][3] += r0 * wv.w;
            acc[1][0] += r1 * wv.x; acc[1][1] += r1 * wv.y;
            acc[1][2] += r1 * wv.z; acc[1][3] += r1 * wv.w;
        }
        __syncthreads();
    }

#pragma unroll
    for (int i = 0; i < 2; i++) {
        int bb = btile + ty * 2 + i;
        float4 o = make_float4(acc[i][0], acc[i][1], acc[i][2], acc[i][3]);
        *reinterpret_cast<float4*>(&g_partial[((size_t)blockIdx.z * Bx + bb) * 320 + ftile + tx * 4]) = o;
    }
}

// ===== K5: combine split-K + gate, LayerNorm(321), classifier =========
__device__ __forceinline__ float blockReduceSum(float val, float* sbuf) {
    int tid = threadIdx.x;
#pragma unroll
    for (int o = 16; o > 0; o >>= 1) val += __shfl_down_sync(0xffffffffu, val, o);
    if ((tid & 31) == 0) sbuf[tid >> 5] = val;
    __syncthreads();
    if (tid < 32) {
        int nw = (blockDim.x + 31) >> 5;
        float r = (tid < nw) ? sbuf[tid] : 0.f;
#pragma unroll
        for (int o = 16; o > 0; o >>= 1) r += __shfl_down_sync(0xffffffffu, r, o);
        if (tid == 0) sbuf[32] = r;
    }
    __syncthreads();
    float out = sbuf[32];
    __syncthreads();
    return out;
}

__global__ void k5_ln_cls(const float* __restrict__ bc,
                          const float* __restrict__ bs,
                          const float* __restrict__ gate,
                          const float* __restrict__ ln_g,
                          const float* __restrict__ ln_b,
                          const float* __restrict__ Wcls,
                          const float* __restrict__ bcls,
                          float* __restrict__ out) {
    __shared__ float sbuf[33];
    int b = blockIdx.x;
    int f = threadIdx.x; // 384 threads
    bool act = (f < FDIMx);

    float x = 0.f;
    if (f < 320) {
        float s = 0.f;
#pragma unroll
        for (int z = 0; z < 16; z++) s += g_partial[((size_t)z * Bx + b) * 320 + f];
        float g = 1.f / (1.f + expf(-gate[0]));
        if (f < CDIMx) x = (s + bc[f]) * (1.f - g);
        else           x = (s + bs[f - CDIMx]) * g;
    } else if (f == 320) {
        x = g_feat[b * FDIMx + 320];
    }

    float S  = blockReduceSum(x, sbuf);
    float SS = blockReduceSum(x * x, sbuf);
    float mean = S / (float)FDIMx;
    float var  = SS / (float)FDIMx - mean * mean;
    float inv  = rsqrtf(var + 1e-5f);

    float nrm = act ? ((x - mean) * inv * ln_g[f] + ln_b[f]) : 0.f;
    float w0 = act ? Wcls[f] : 0.f;
    float w1 = act ? Wcls[FDIMx + f] : 0.f;

    float s0 = blockReduceSum(nrm * w0, sbuf);
    float s1 = blockReduceSum(nrm * w1, sbuf);
    if (f == 0) {
        out[b * 2 + 0] = s0 + bcls[0];
        out[b * 2 + 1] = s1 + bcls[1];
    }
}

// =================================== launch ======================================
extern "C" void kernel_launch(void* const* d_in, const int* in_sizes, int n_in,
                              void* d_out, int out_size) {
    const float* H    = (const float*)d_in[0];
    const int*   tt   = (const int*)d_in[1];
    const int*   m    = (const int*)d_in[2];
    const float* Wc   = (const float*)d_in[3];
    const float* bc   = (const float*)d_in[4];
    const float* Ws   = (const float*)d_in[5];
    const float* bs   = (const float*)d_in[6];
    const float* gate = (const float*)d_in[7];
    const float* ln_g = (const float*)d_in[8];
    const float* ln_b = (const float*)d_in[9];
    const float* Wcls = (const float*)d_in[10];
    const float* bcls = (const float*)d_in[11];
    const float* proj = (const float*)d_in[12];
    float* out = (float*)d_out;

    static bool attr_set = false;
    if (!attr_set) {
        cudaFuncSetAttribute(k2_mma, cudaFuncAttributeMaxDynamicSharedMemorySize, K2_SMEM);
        attr_set = true;
    }

    k1_stats<<<dim3(Bx, 3), 256>>>(H, tt, m);
    k2_mma<<<dim3(Bx, 2), 256, K2_SMEM>>>(H, proj);
    k3_sort<<<dim3(16, Bx), 256>>>(tt, m);
    k4a_featgemm<<<dim3(5, 4, 16), 256>>>(Wc, Ws);
    k5_ln_cls<<<Bx, 384>>>(bc, bs, gate, ln_g, ln_b, Wcls, bcls, out);
}